// round 12
// baseline (speedup 1.0000x reference)
#include <cuda_runtime.h>
#include <math.h>

#define NN 50000
#define EE 800000
#define HH 64
#define NBINS (NN * 3)          // 150000 (node,rel) bins
#define SCAN_BLOCKS 147         // ceil(150000 / 1024)

typedef unsigned long long ull;

// ---------------- device scratch (no allocations allowed) ----------------
__device__ float         g_agg[3 * NN * HH];   // per-relation gather sums (layers 1,2)
__device__ float         g_agg0[NN * 9];       // layer0: [node][rel][3]
__device__ int           g_cnt[NBINS];         // per-(node,rel) edge counts
__device__ float         g_inv[NBINS];         // 1/max(cnt,1)
__device__ unsigned char g_et[EE];             // edge type 0..2
__device__ int           g_esrc[EE];           // CSR: src node per sorted slot
__device__ int           g_off[NBINS + 1];     // CSR offsets
__device__ int           g_cursor[NBINS];      // fill cursors
__device__ int           g_bsum[256];          // block sums for scan
__device__ float         g_h[3 * NN * HH];     // h1,h2,h3
__device__ float         g_pre[NN * HH];       // GEMM pre-activation scratch
__device__ float         g_pab[NN * HH];       // [n][0:32]=h3@Wa+b1, [n][32:64]=h3@Wb

__device__ __forceinline__ ull splat_f(float x) {
    unsigned int u = __float_as_uint(x);
    return ((ull)u << 32) | (ull)u;
}

// ---------------- kernel 1: edge type + counts + layer0 scatter (fused) ----------------
__global__ void k_edge_prep(const int* __restrict__ ei, const float* __restrict__ ea,
                            const float* __restrict__ x) {
    int e = blockIdx.x * blockDim.x + threadIdx.x;
    if (e >= EE) return;
    const float q1 = log1pf(5000.0f);
    const float q2 = log1pf(10000.0f);
    float dist = ea[e * 6];
    int t = (dist > q1) + (dist > q2);
    g_et[e] = (unsigned char)t;
    int s = ei[e], d = ei[EE + e];
    atomicAdd(&g_cnt[d * 3 + t], 1);
    float* dstp = &g_agg0[d * 9 + t * 3];
    atomicAdd(dstp + 0, x[s * 3 + 0]);
    atomicAdd(dstp + 1, x[s * 3 + 1]);
    atomicAdd(dstp + 2, x[s * 3 + 2]);
}

__global__ void k_inv() {
    int i = blockIdx.x * blockDim.x + threadIdx.x;
    if (i >= NBINS) return;
    g_inv[i] = 1.0f / fmaxf((float)g_cnt[i], 1.0f);
}

// ---------------- CSR scan: 3 kernels ----------------
__global__ void k_scan1() {
    int t = threadIdx.x, blk = blockIdx.x;
    int base = blk * 1024 + t * 4;
    int s = 0;
#pragma unroll
    for (int i = 0; i < 4; i++) {
        int b = base + i;
        if (b < NBINS) s += g_cnt[b];
    }
    __shared__ int sh[256];
    sh[t] = s; __syncthreads();
    for (int off = 128; off > 0; off >>= 1) {
        if (t < off) sh[t] += sh[t + off];
        __syncthreads();
    }
    if (t == 0) g_bsum[blk] = sh[0];
}

__global__ void k_scan2() {
    int t = threadIdx.x;
    int v = (t < SCAN_BLOCKS) ? g_bsum[t] : 0;
    __shared__ int sh[256];
    sh[t] = v; __syncthreads();
    for (int off = 1; off < 256; off <<= 1) {
        int x = (t >= off) ? sh[t - off] : 0;
        __syncthreads();
        sh[t] += x;
        __syncthreads();
    }
    if (t < SCAN_BLOCKS) g_bsum[t] = sh[t] - v;   // exclusive
    if (t == 0) g_off[NBINS] = EE;
}

__global__ void k_scan3() {
    int t = threadIdx.x, blk = blockIdx.x;
    int base = blk * 1024 + t * 4;
    int c[4]; int s = 0;
#pragma unroll
    for (int i = 0; i < 4; i++) {
        int b = base + i;
        c[i] = (b < NBINS) ? g_cnt[b] : 0;
        s += c[i];
    }
    __shared__ int sh[256];
    sh[t] = s; __syncthreads();
    for (int off = 1; off < 256; off <<= 1) {
        int x = (t >= off) ? sh[t - off] : 0;
        __syncthreads();
        sh[t] += x;
        __syncthreads();
    }
    int run = g_bsum[blk] + (sh[t] - s);
#pragma unroll
    for (int i = 0; i < 4; i++) {
        int b = base + i;
        if (b < NBINS) { g_off[b] = run; g_cursor[b] = run; run += c[i]; }
    }
}

__global__ void k_fill(const int* __restrict__ ei) {
    int e = blockIdx.x * blockDim.x + threadIdx.x;
    if (e >= EE) return;
    int s = ei[e], d = ei[EE + e];
    int r = g_et[e];
    int pos = atomicAdd(&g_cursor[d * 3 + r], 1);
    g_esrc[pos] = s;
}

// ---------------- layer 0 node: rgcn + relu + residual(x@res_w) + LN ----------------
__global__ void k_node0(const float* __restrict__ x,
                        const float* __restrict__ w0, const float* __restrict__ root0,
                        const float* __restrict__ b0,
                        const float* __restrict__ resw, const float* __restrict__ resb,
                        const float* __restrict__ gam, const float* __restrict__ bet,
                        float* __restrict__ out) {
    int tid = threadIdx.x;
    int node = blockIdx.x * 4 + (tid >> 6);
    int j = tid & 63;
    if (node >= NN) return;

    float x0 = x[node * 3 + 0], x1 = x[node * 3 + 1], x2 = x[node * 3 + 2];
    float acc = b0[j];
    acc = fmaf(x0, root0[0 * 64 + j], acc);
    acc = fmaf(x1, root0[1 * 64 + j], acc);
    acc = fmaf(x2, root0[2 * 64 + j], acc);
#pragma unroll
    for (int r = 0; r < 3; r++) {
        float cf = g_inv[node * 3 + r];
#pragma unroll
        for (int i = 0; i < 3; i++) {
            float a = g_agg0[node * 9 + r * 3 + i] * cf;
            acc = fmaf(a, w0[(r * 3 + i) * 64 + j], acc);
        }
    }
    float res = resb[j];
    res = fmaf(x0, resw[0 * 64 + j], res);
    res = fmaf(x1, resw[1 * 64 + j], res);
    res = fmaf(x2, resw[2 * 64 + j], res);
    float v = fmaxf(acc, 0.0f) + res;

    float s = v, q = v * v;
#pragma unroll
    for (int off = 16; off > 0; off >>= 1) {
        s += __shfl_xor_sync(0xffffffff, s, off);
        q += __shfl_xor_sync(0xffffffff, q, off);
    }
    __shared__ float sred[8], qred[8];
    int warp = tid >> 5;
    if ((tid & 31) == 0) { sred[warp] = s; qred[warp] = q; }
    __syncthreads();
    int grp = warp >> 1;
    float ts = sred[grp * 2] + sred[grp * 2 + 1];
    float tq = qred[grp * 2] + qred[grp * 2 + 1];
    float mu = ts * (1.0f / 64.0f);
    float var = tq * (1.0f / 64.0f) - mu * mu;
    float rstd = rsqrtf(var + 1e-5f);
    out[node * 64 + j] = (v - mu) * rstd * gam[j] + bet[j];
}

// ---------------- layers 1/2 gather-aggregate via CSR (no atomics) ----------------
__global__ void k_aggregate(const float* __restrict__ h) {
    int tid = threadIdx.x;
    int node = blockIdx.x * 4 + (tid >> 6);
    int j = tid & 63;
    if (node >= NN) return;
#pragma unroll
    for (int r = 0; r < 3; r++) {
        int bin = node * 3 + r;
        int a = g_off[bin], b = g_off[bin + 1];
        float acc0 = 0.0f, acc1 = 0.0f, acc2 = 0.0f, acc3 = 0.0f;
        int e = a;
        for (; e + 3 < b; e += 4) {
            int s0 = g_esrc[e], s1 = g_esrc[e + 1];
            int s2 = g_esrc[e + 2], s3 = g_esrc[e + 3];
            acc0 += h[s0 * 64 + j];
            acc1 += h[s1 * 64 + j];
            acc2 += h[s2 * 64 + j];
            acc3 += h[s3 * 64 + j];
        }
        for (; e < b; e++) acc0 += h[g_esrc[e] * 64 + j];
        g_agg[(r * NN + node) * 64 + j] = (acc0 + acc1) + (acc2 + acc3);
    }
}

// ---------------- tiled GEMM: [64 nodes x 256] @ [256 x 64], f32x2 ----------------
// dyn smem: As_T[64*66] floats | Bs_dup[64*64] ulls (splatted) = 49.6KB
#define GEMM_SMEM_BYTES (64 * 66 * 4 + 64 * 64 * 8)
__global__ void k_rgcn_gemm(const float* __restrict__ xi,
                            const float* __restrict__ root, const float* __restrict__ W,
                            const float* __restrict__ bias, float* __restrict__ outp) {
    extern __shared__ float sg[];
    float* As_T  = sg;                      // [k][row] stride 66
    ull*   Bs_dup = (ull*)(sg + 64 * 66);   // [k][n] splatted

    int tid = threadIdx.x;
    int n0 = blockIdx.x * 64;
    int tx = tid & 15, ty = tid >> 4;
    int c4 = tx * 4, ty4 = ty * 4;
    ull A[4][2] = {};   // A[c][rowpair]

    for (int ko = 0; ko < 256; ko += 64) {
#pragma unroll
        for (int t = 0; t < 16; t++) {
            int idx = tid + t * 256;
            int row = idx >> 6, k = idx & 63;
            int n = n0 + row;
            float v = 0.0f;
            if (n < NN) {
                if (ko == 0) v = xi[n * 64 + k];
                else {
                    int r = (ko >> 6) - 1;
                    v = g_agg[(r * NN + n) * 64 + k] * g_inv[n * 3 + r];
                }
            }
            As_T[k * 66 + row] = v;
            float w;
            if (ko == 0) w = root[idx];
            else {
                int r = (ko >> 6) - 1;
                w = W[r * 4096 + idx];
            }
            Bs_dup[idx] = splat_f(w);
        }
        __syncthreads();
#pragma unroll 8
        for (int kk = 0; kk < 64; kk++) {
            ull a01 = *(const ull*)&As_T[kk * 66 + ty4];
            ull a23 = *(const ull*)&As_T[kk * 66 + ty4 + 2];
            ulonglong2 b01 = *(const ulonglong2*)&Bs_dup[kk * 64 + c4];
            ulonglong2 b23 = *(const ulonglong2*)&Bs_dup[kk * 64 + c4 + 2];
            asm("fma.rn.f32x2 %0, %1, %2, %0;" : "+l"(A[0][0]) : "l"(a01), "l"(b01.x));
            asm("fma.rn.f32x2 %0, %1, %2, %0;" : "+l"(A[0][1]) : "l"(a23), "l"(b01.x));
            asm("fma.rn.f32x2 %0, %1, %2, %0;" : "+l"(A[1][0]) : "l"(a01), "l"(b01.y));
            asm("fma.rn.f32x2 %0, %1, %2, %0;" : "+l"(A[1][1]) : "l"(a23), "l"(b01.y));
            asm("fma.rn.f32x2 %0, %1, %2, %0;" : "+l"(A[2][0]) : "l"(a01), "l"(b23.x));
            asm("fma.rn.f32x2 %0, %1, %2, %0;" : "+l"(A[2][1]) : "l"(a23), "l"(b23.x));
            asm("fma.rn.f32x2 %0, %1, %2, %0;" : "+l"(A[3][0]) : "l"(a01), "l"(b23.y));
            asm("fma.rn.f32x2 %0, %1, %2, %0;" : "+l"(A[3][1]) : "l"(a23), "l"(b23.y));
        }
        __syncthreads();
    }
    float o[4][4];
#pragma unroll
    for (int cc = 0; cc < 4; cc++) {
        float lo, hi;
        asm("mov.b64 {%0, %1}, %2;" : "=f"(lo), "=f"(hi) : "l"(A[cc][0]));
        o[0][cc] = lo; o[1][cc] = hi;
        asm("mov.b64 {%0, %1}, %2;" : "=f"(lo), "=f"(hi) : "l"(A[cc][1]));
        o[2][cc] = lo; o[3][cc] = hi;
    }
    float4 bv = *(const float4*)&bias[c4];
#pragma unroll
    for (int i = 0; i < 4; i++) {
        int n = n0 + ty4 + i;
        if (n < NN) {
            *(float4*)&outp[n * 64 + c4] =
                make_float4(o[i][0] + bv.x, o[i][1] + bv.y, o[i][2] + bv.z, o[i][3] + bv.w);
        }
    }
}

// ---------------- relu + residual + LN ----------------
__global__ void k_relu_res_ln(const float* __restrict__ pre, const float* __restrict__ resid,
                              const float* __restrict__ gam, const float* __restrict__ bet,
                              float* __restrict__ out) {
    int tid = threadIdx.x;
    int node = blockIdx.x * 4 + (tid >> 6);
    int j = tid & 63;
    if (node >= NN) return;
    float v = fmaxf(pre[node * 64 + j], 0.0f) + resid[node * 64 + j];
    float s = v, q = v * v;
#pragma unroll
    for (int off = 16; off > 0; off >>= 1) {
        s += __shfl_xor_sync(0xffffffff, s, off);
        q += __shfl_xor_sync(0xffffffff, q, off);
    }
    __shared__ float sred[8], qred[8];
    int warp = tid >> 5;
    if ((tid & 31) == 0) { sred[warp] = s; qred[warp] = q; }
    __syncthreads();
    int grp = warp >> 1;
    float ts = sred[grp * 2] + sred[grp * 2 + 1];
    float tq = qred[grp * 2] + qred[grp * 2 + 1];
    float mu = ts * (1.0f / 64.0f);
    float var = tq * (1.0f / 64.0f) - mu * mu;
    float rstd = rsqrtf(var + 1e-5f);
    out[node * 64 + j] = (v - mu) * rstd * gam[j] + bet[j];
}

// ---------------- pab: [50K x 64] @ [64 x 64], f32x2 ----------------
__global__ void k_pab2(const float* __restrict__ h3, const float* __restrict__ dw1,
                       const float* __restrict__ db1, float* __restrict__ pab) {
    extern __shared__ float sg[];
    float* As_T  = sg;
    ull*   Bs_dup = (ull*)(sg + 64 * 66);

    int tid = threadIdx.x;
    int n0 = blockIdx.x * 64;
    int tx = tid & 15, ty = tid >> 4;
    int c4 = tx * 4, ty4 = ty * 4;
    ull A[4][2] = {};

#pragma unroll
    for (int t = 0; t < 16; t++) {
        int idx = tid + t * 256;
        int row = idx >> 6, k = idx & 63;
        int n = n0 + row;
        As_T[k * 66 + row] = (n < NN) ? h3[n * 64 + k] : 0.0f;
        float w = (k < 32) ? dw1[row * 32 + k] : dw1[(64 + row) * 32 + (k - 32)];
        Bs_dup[idx] = splat_f(w);
    }
    __syncthreads();
#pragma unroll 8
    for (int kk = 0; kk < 64; kk++) {
        ull a01 = *(const ull*)&As_T[kk * 66 + ty4];
        ull a23 = *(const ull*)&As_T[kk * 66 + ty4 + 2];
        ulonglong2 b01 = *(const ulonglong2*)&Bs_dup[kk * 64 + c4];
        ulonglong2 b23 = *(const ulonglong2*)&Bs_dup[kk * 64 + c4 + 2];
        asm("fma.rn.f32x2 %0, %1, %2, %0;" : "+l"(A[0][0]) : "l"(a01), "l"(b01.x));
        asm("fma.rn.f32x2 %0, %1, %2, %0;" : "+l"(A[0][1]) : "l"(a23), "l"(b01.x));
        asm("fma.rn.f32x2 %0, %1, %2, %0;" : "+l"(A[1][0]) : "l"(a01), "l"(b01.y));
        asm("fma.rn.f32x2 %0, %1, %2, %0;" : "+l"(A[1][1]) : "l"(a23), "l"(b01.y));
        asm("fma.rn.f32x2 %0, %1, %2, %0;" : "+l"(A[2][0]) : "l"(a01), "l"(b23.x));
        asm("fma.rn.f32x2 %0, %1, %2, %0;" : "+l"(A[2][1]) : "l"(a23), "l"(b23.x));
        asm("fma.rn.f32x2 %0, %1, %2, %0;" : "+l"(A[3][0]) : "l"(a01), "l"(b23.y));
        asm("fma.rn.f32x2 %0, %1, %2, %0;" : "+l"(A[3][1]) : "l"(a23), "l"(b23.y));
    }
    float o[4][4];
#pragma unroll
    for (int cc = 0; cc < 4; cc++) {
        float lo, hi;
        asm("mov.b64 {%0, %1}, %2;" : "=f"(lo), "=f"(hi) : "l"(A[cc][0]));
        o[0][cc] = lo; o[1][cc] = hi;
        asm("mov.b64 {%0, %1}, %2;" : "=f"(lo), "=f"(hi) : "l"(A[cc][1]));
        o[2][cc] = lo; o[3][cc] = hi;
    }
    float4 bv = make_float4(0.f, 0.f, 0.f, 0.f);
    if (c4 < 32) bv = *(const float4*)&db1[c4];
#pragma unroll
    for (int i = 0; i < 4; i++) {
        int n = n0 + ty4 + i;
        if (n < NN) {
            *(float4*)&pab[n * 64 + c4] =
                make_float4(o[i][0] + bv.x, o[i][1] + bv.y, o[i][2] + bv.z, o[i][3] + bv.w);
        }
    }
}

// ---------------- decoder: block-level GEMM over 64-edge tiles (R8 config) ----------------
// smem (floats): Bs[128*32] | F_T[128*66] | zS[32*66] | W2[512] | We[192]
//                | eS[384] | sIdx/dIdx int[64] each  => ~63.5KB, 3 CTAs/SM
#define DEC_SMEM_FLOATS (4096 + 8448 + 2112 + 512 + 192 + 384)
#define DEC_SMEM_BYTES  (DEC_SMEM_FLOATS * 4 + 128 * 4)

__global__ void k_decode_gemm(const int* __restrict__ ei, const float* __restrict__ ea,
                              const float* __restrict__ h3, const float* __restrict__ pab,
                              const float* __restrict__ dw1,
                              const float* __restrict__ dw2, const float* __restrict__ db2,
                              const float* __restrict__ dw3, const float* __restrict__ db3,
                              float* __restrict__ out) {
    extern __shared__ float smf[];
    float* Bs  = smf;               // [128][32] = dw1 rows 128..255
    float* F_T = Bs + 4096;         // [128][66] features^T
    float* zS  = F_T + 8448;        // [32][66]  z^T
    float* W2  = zS + 2112;         // [32][16]
    float* Wes = W2 + 512;          // [6][32]
    float* eS  = Wes + 192;         // [64][6]
    int* sIdx  = (int*)(eS + 384);  // [64]
    int* dIdx  = sIdx + 64;         // [64]

    int tid = threadIdx.x;
    for (int i = tid; i < 4096; i += 256) Bs[i] = dw1[128 * 32 + i];
    for (int i = tid; i < 512; i += 256) W2[i] = dw2[i];
    for (int i = tid; i < 192; i += 256) Wes[i] = dw1[256 * 32 + i];

    int kb = tid & 63, gb = tid >> 6;          // build phase
    int tx = tid & 15, ty = tid >> 4;          // layer1 tiling
    int c = 2 * tx, ty4 = ty * 4;
    int tx2 = tid & 7, ty2 = tid >> 3;         // layer2 tiling
    int c2 = 2 * tx2;
    float b2x = db2[c2], b2y = db2[c2 + 1];
    ull B2X, B2Y;
    asm("mov.b64 %0, {%1, %1};" : "=l"(B2X) : "f"(b2x));
    asm("mov.b64 %0, {%1, %1};" : "=l"(B2Y) : "f"(b2y));
    float w3x = dw3[c2], w3y = dw3[c2 + 1];
    float bias3 = db3[0];
    __syncthreads();

    for (int t = blockIdx.x; t < EE / 64; t += gridDim.x) {
        int e0 = t * 64;
        if (tid < 64) { sIdx[tid] = ei[e0 + tid]; dIdx[tid] = ei[EE + e0 + tid]; }
        for (int i = tid; i < 384; i += 256) eS[i] = ea[e0 * 6 + i];
        __syncthreads();

        // ---- build F_T: k<64 -> |hs-hd|, k>=64 -> hs*hd (unroll 8: MLP~16) ----
#pragma unroll 8
        for (int p = 0; p < 16; p++) {
            int eL = p * 4 + gb;
            int sm = sIdx[eL], dm = dIdx[eL];
            float a = h3[sm * 64 + kb], b = h3[dm * 64 + kb];
            F_T[kb * 66 + eL]        = fabsf(a - b);
            F_T[(64 + kb) * 66 + eL] = a * b;
        }

        // ---- init accumulators BEFORE sync: pab gather latency absorbed by barrier ----
        float initv[4][2];
#pragma unroll
        for (int i = 0; i < 4; i++) {
            int m = ty4 + i;
            int sm = sIdx[m], dm = dIdx[m];
            float2 pa = *(const float2*)&pab[sm * 64 + c];
            float2 pb = *(const float2*)&pab[dm * 64 + 32 + c];
            float v0 = pa.x + pb.x, v1 = pa.y + pb.y;
#pragma unroll
            for (int q = 0; q < 6; q++) {
                float eq = eS[m * 6 + q];
                float2 w = *(const float2*)&Wes[q * 32 + c];
                v0 = fmaf(eq, w.x, v0);
                v1 = fmaf(eq, w.y, v1);
            }
            initv[i][0] = v0; initv[i][1] = v1;
        }
        ull A00, A01, A10, A11;
        asm("mov.b64 %0, {%1, %2};" : "=l"(A00) : "f"(initv[0][0]), "f"(initv[1][0]));
        asm("mov.b64 %0, {%1, %2};" : "=l"(A01) : "f"(initv[0][1]), "f"(initv[1][1]));
        asm("mov.b64 %0, {%1, %2};" : "=l"(A10) : "f"(initv[2][0]), "f"(initv[3][0]));
        asm("mov.b64 %0, {%1, %2};" : "=l"(A11) : "f"(initv[2][1]), "f"(initv[3][1]));
        __syncthreads();

        // ---- layer 1: [64 x 128] @ [128 x 32] ----
#pragma unroll 8
        for (int kk = 0; kk < 128; kk++) {
            ull a01 = *(const ull*)&F_T[kk * 66 + ty4];
            ull a23 = *(const ull*)&F_T[kk * 66 + ty4 + 2];
            float2 b = *(const float2*)&Bs[kk * 32 + c];
            ull bx, by;
            asm("mov.b64 %0, {%1, %1};" : "=l"(bx) : "f"(b.x));
            asm("mov.b64 %0, {%1, %1};" : "=l"(by) : "f"(b.y));
            asm("fma.rn.f32x2 %0, %1, %2, %0;" : "+l"(A00) : "l"(a01), "l"(bx));
            asm("fma.rn.f32x2 %0, %1, %2, %0;" : "+l"(A01) : "l"(a01), "l"(by));
            asm("fma.rn.f32x2 %0, %1, %2, %0;" : "+l"(A10) : "l"(a23), "l"(bx));
            asm("fma.rn.f32x2 %0, %1, %2, %0;" : "+l"(A11) : "l"(a23), "l"(by));
        }
        {
            float u0, u1;
            asm("mov.b64 {%0, %1}, %2;" : "=f"(u0), "=f"(u1) : "l"(A00));
            *(float2*)&zS[c * 66 + ty4] = make_float2(fmaxf(u0, 0.f), fmaxf(u1, 0.f));
            asm("mov.b64 {%0, %1}, %2;" : "=f"(u0), "=f"(u1) : "l"(A10));
            *(float2*)&zS[c * 66 + ty4 + 2] = make_float2(fmaxf(u0, 0.f), fmaxf(u1, 0.f));
            asm("mov.b64 {%0, %1}, %2;" : "=f"(u0), "=f"(u1) : "l"(A01));
            *(float2*)&zS[(c + 1) * 66 + ty4] = make_float2(fmaxf(u0, 0.f), fmaxf(u1, 0.f));
            asm("mov.b64 {%0, %1}, %2;" : "=f"(u0), "=f"(u1) : "l"(A11));
            *(float2*)&zS[(c + 1) * 66 + ty4 + 2] = make_float2(fmaxf(u0, 0.f), fmaxf(u1, 0.f));
        }
        __syncthreads();

        // ---- layer 2: [64 x 32] @ [32 x 16], edge pair (2*ty2, 2*ty2+1) ----
        ull Z0 = B2X, Z1 = B2Y;
#pragma unroll 8
        for (int kk = 0; kk < 32; kk++) {
            ull zp = *(const ull*)&zS[kk * 66 + 2 * ty2];
            float2 w = *(const float2*)&W2[kk * 16 + c2];
            ull wx, wy;
            asm("mov.b64 %0, {%1, %1};" : "=l"(wx) : "f"(w.x));
            asm("mov.b64 %0, {%1, %1};" : "=l"(wy) : "f"(w.y));
            asm("fma.rn.f32x2 %0, %1, %2, %0;" : "+l"(Z0) : "l"(zp), "l"(wx));
            asm("fma.rn.f32x2 %0, %1, %2, %0;" : "+l"(Z1) : "l"(zp), "l"(wy));
        }
        float q00, q10, q01, q11;
        asm("mov.b64 {%0, %1}, %2;" : "=f"(q00), "=f"(q10) : "l"(Z0));
        asm("mov.b64 {%0, %1}, %2;" : "=f"(q01), "=f"(q11) : "l"(Z1));
        float o0 = fmaxf(q00, 0.f) * w3x + fmaxf(q01, 0.f) * w3y;
        float o1 = fmaxf(q10, 0.f) * w3x + fmaxf(q11, 0.f) * w3y;
        o0 += __shfl_xor_sync(0xffffffff, o0, 4);
        o0 += __shfl_xor_sync(0xffffffff, o0, 2);
        o0 += __shfl_xor_sync(0xffffffff, o0, 1);
        o1 += __shfl_xor_sync(0xffffffff, o1, 4);
        o1 += __shfl_xor_sync(0xffffffff, o1, 2);
        o1 += __shfl_xor_sync(0xffffffff, o1, 1);
        if (tx2 == 0) {
            out[e0 + 2 * ty2]     = o0 + bias3;
            out[e0 + 2 * ty2 + 1] = o1 + bias3;
        }
        __syncthreads();
    }
}

// ---------------- host launch ----------------
extern "C" void kernel_launch(void* const* d_in, const int* in_sizes, int n_in,
                              void* d_out, int out_size) {
    const float* x     = (const float*)d_in[0];
    const int*   ei    = (const int*)d_in[1];
    const float* ea    = (const float*)d_in[2];
    const float* w0    = (const float*)d_in[3];
    const float* root0 = (const float*)d_in[4];
    const float* b0    = (const float*)d_in[5];
    const float* w1    = (const float*)d_in[6];
    const float* root1 = (const float*)d_in[7];
    const float* b1    = (const float*)d_in[8];
    const float* w2    = (const float*)d_in[9];
    const float* root2 = (const float*)d_in[10];
    const float* b2    = (const float*)d_in[11];
    const float* lng0  = (const float*)d_in[12];
    const float* lnb0  = (const float*)d_in[13];
    const float* lng1  = (const float*)d_in[14];
    const float* lnb1  = (const float*)d_in[15];
    const float* lng2  = (const float*)d_in[16];
    const float* lnb2  = (const float*)d_in[17];
    const float* resw  = (const float*)d_in[18];
    const float* resb  = (const float*)d_in[19];
    const float* dw1   = (const float*)d_in[20];
    const float* db1   = (const float*)d_in[21];
    const float* dw2   = (const float*)d_in[22];
    const float* db2   = (const float*)d_in[23];
    const float* dw3   = (const float*)d_in[24];
    const float* db3   = (const float*)d_in[25];
    float* out = (float*)d_out;

    static int configured = 0;
    if (!configured) {
        cudaFuncSetAttribute(k_decode_gemm,
                             cudaFuncAttributeMaxDynamicSharedMemorySize, DEC_SMEM_BYTES);
        cudaFuncSetAttribute(k_rgcn_gemm,
                             cudaFuncAttributeMaxDynamicSharedMemorySize, GEMM_SMEM_BYTES);
        cudaFuncSetAttribute(k_pab2,
                             cudaFuncAttributeMaxDynamicSharedMemorySize, GEMM_SMEM_BYTES);
        configured = 1;
    }

    void *p_cnt, *p_agg0, *p_h, *p_pre, *p_pab;
    cudaGetSymbolAddress(&p_cnt,  g_cnt);
    cudaGetSymbolAddress(&p_agg0, g_agg0);
    cudaGetSymbolAddress(&p_h,    g_h);
    cudaGetSymbolAddress(&p_pre,  g_pre);
    cudaGetSymbolAddress(&p_pab,  g_pab);
    float* h1  = (float*)p_h;
    float* h2  = h1 + NN * 64;
    float* h3  = h2 + NN * 64;
    float* pre = (float*)p_pre;
    float* pab = (float*)p_pab;

    cudaMemsetAsync(p_cnt,  0, sizeof(int)   * NBINS);
    cudaMemsetAsync(p_agg0, 0, sizeof(float) * NN * 9);

    // fused: edge type + counts + layer0 scatter
    k_edge_prep<<<(EE + 255) / 256, 256>>>(ei, ea, x);
    k_inv<<<(NBINS + 255) / 256, 256>>>();

    // CSR build
    k_scan1<<<SCAN_BLOCKS, 256>>>();
    k_scan2<<<1, 256>>>();
    k_scan3<<<SCAN_BLOCKS, 256>>>();
    k_fill<<<(EE + 255) / 256, 256>>>(ei);

    // layer 0
    k_node0<<<NN / 4, 256>>>(x, w0, root0, b0, resw, resb, lng0, lnb0, h1);

    // layer 1
    k_aggregate<<<NN / 4, 256>>>(h1);
    k_rgcn_gemm<<<(NN + 63) / 64, 256, GEMM_SMEM_BYTES>>>(h1, root1, w1, b1, pre);
    k_relu_res_ln<<<NN / 4, 256>>>(pre, h1, lng1, lnb1, h2);

    // layer 2
    k_aggregate<<<NN / 4, 256>>>(h2);
    k_rgcn_gemm<<<(NN + 63) / 64, 256, GEMM_SMEM_BYTES>>>(h2, root2, w2, b2, pre);
    k_relu_res_ln<<<NN / 4, 256>>>(pre, h2, lng2, lnb2, h3);

    // decoder
    k_pab2<<<(NN + 63) / 64, 256, GEMM_SMEM_BYTES>>>(h3, dw1, db1, pab);
    k_decode_gemm<<<444, 256, DEC_SMEM_BYTES>>>(ei, ea, h3, pab, dw1, dw2, db2, dw3, db3, out);
}

// round 16
// speedup vs baseline: 1.3387x; 1.3387x over previous
#include <cuda_runtime.h>
#include <math.h>

#define NN 50000
#define EE 800000
#define HH 64
#define NBINS (NN * 3)          // 150000 (node,rel) bins
#define SCAN_BLOCKS 147         // ceil(150000 / 1024)

typedef unsigned long long ull;

// ---------------- device scratch (no allocations allowed) ----------------
__device__ float         g_agg[3 * NN * HH];   // per-relation gather sums (layers 1,2)
__device__ float         g_agg0[NN * 9];       // layer0: [node][rel][3]
__device__ int           g_cnt[NBINS];         // per-(node,rel) edge counts
__device__ float         g_inv[NBINS];         // 1/max(cnt,1)
__device__ unsigned char g_et[EE];             // edge type 0..2
__device__ int           g_esrc[EE];           // CSR: src node per sorted slot
__device__ int           g_off[NBINS + 1];     // CSR offsets
__device__ int           g_cursor[NBINS];      // fill cursors
__device__ int           g_bsum[256];          // block sums for scan
__device__ float         g_h[3 * NN * HH];     // h1,h2,h3
__device__ float         g_pab[NN * HH];       // [n][0:32]=h3@Wa+b1, [n][32:64]=h3@Wb

// ---------------- kernel 1: edge type + counts + layer0 scatter (fused) ----------------
__global__ void k_edge_prep(const int* __restrict__ ei, const float* __restrict__ ea,
                            const float* __restrict__ x) {
    int e = blockIdx.x * blockDim.x + threadIdx.x;
    if (e >= EE) return;
    const float q1 = log1pf(5000.0f);
    const float q2 = log1pf(10000.0f);
    float dist = ea[e * 6];
    int t = (dist > q1) + (dist > q2);
    g_et[e] = (unsigned char)t;
    int s = ei[e], d = ei[EE + e];
    atomicAdd(&g_cnt[d * 3 + t], 1);
    float* dstp = &g_agg0[d * 9 + t * 3];
    atomicAdd(dstp + 0, x[s * 3 + 0]);
    atomicAdd(dstp + 1, x[s * 3 + 1]);
    atomicAdd(dstp + 2, x[s * 3 + 2]);
}

// ---------------- CSR scan: 3 kernels (scan3 also emits g_inv) ----------------
__global__ void k_scan1() {
    int t = threadIdx.x, blk = blockIdx.x;
    int base = blk * 1024 + t * 4;
    int s = 0;
#pragma unroll
    for (int i = 0; i < 4; i++) {
        int b = base + i;
        if (b < NBINS) s += g_cnt[b];
    }
    __shared__ int sh[256];
    sh[t] = s; __syncthreads();
    for (int off = 128; off > 0; off >>= 1) {
        if (t < off) sh[t] += sh[t + off];
        __syncthreads();
    }
    if (t == 0) g_bsum[blk] = sh[0];
}

__global__ void k_scan2() {
    int t = threadIdx.x;
    int v = (t < SCAN_BLOCKS) ? g_bsum[t] : 0;
    __shared__ int sh[256];
    sh[t] = v; __syncthreads();
    for (int off = 1; off < 256; off <<= 1) {
        int x = (t >= off) ? sh[t - off] : 0;
        __syncthreads();
        sh[t] += x;
        __syncthreads();
    }
    if (t < SCAN_BLOCKS) g_bsum[t] = sh[t] - v;   // exclusive
    if (t == 0) g_off[NBINS] = EE;
}

__global__ void k_scan3() {
    int t = threadIdx.x, blk = blockIdx.x;
    int base = blk * 1024 + t * 4;
    int c[4]; int s = 0;
#pragma unroll
    for (int i = 0; i < 4; i++) {
        int b = base + i;
        c[i] = (b < NBINS) ? g_cnt[b] : 0;
        s += c[i];
    }
    __shared__ int sh[256];
    sh[t] = s; __syncthreads();
    for (int off = 1; off < 256; off <<= 1) {
        int x = (t >= off) ? sh[t - off] : 0;
        __syncthreads();
        sh[t] += x;
        __syncthreads();
    }
    int run = g_bsum[blk] + (sh[t] - s);
#pragma unroll
    for (int i = 0; i < 4; i++) {
        int b = base + i;
        if (b < NBINS) {
            g_off[b] = run; g_cursor[b] = run; run += c[i];
            g_inv[b] = 1.0f / fmaxf((float)c[i], 1.0f);   // fused: was k_inv
        }
    }
}

__global__ void k_fill(const int* __restrict__ ei) {
    int e = blockIdx.x * blockDim.x + threadIdx.x;
    if (e >= EE) return;
    int s = ei[e], d = ei[EE + e];
    int r = g_et[e];
    int pos = atomicAdd(&g_cursor[d * 3 + r], 1);
    g_esrc[pos] = s;
}

// ---------------- layer 0 node: rgcn + relu + residual(x@res_w) + LN ----------------
__global__ void k_node0(const float* __restrict__ x,
                        const float* __restrict__ w0, const float* __restrict__ root0,
                        const float* __restrict__ b0,
                        const float* __restrict__ resw, const float* __restrict__ resb,
                        const float* __restrict__ gam, const float* __restrict__ bet,
                        float* __restrict__ out) {
    int tid = threadIdx.x;
    int node = blockIdx.x * 4 + (tid >> 6);
    int j = tid & 63;
    if (node >= NN) return;

    float x0 = x[node * 3 + 0], x1 = x[node * 3 + 1], x2 = x[node * 3 + 2];
    float acc = b0[j];
    acc = fmaf(x0, root0[0 * 64 + j], acc);
    acc = fmaf(x1, root0[1 * 64 + j], acc);
    acc = fmaf(x2, root0[2 * 64 + j], acc);
#pragma unroll
    for (int r = 0; r < 3; r++) {
        float cf = g_inv[node * 3 + r];
#pragma unroll
        for (int i = 0; i < 3; i++) {
            float a = g_agg0[node * 9 + r * 3 + i] * cf;
            acc = fmaf(a, w0[(r * 3 + i) * 64 + j], acc);
        }
    }
    float res = resb[j];
    res = fmaf(x0, resw[0 * 64 + j], res);
    res = fmaf(x1, resw[1 * 64 + j], res);
    res = fmaf(x2, resw[2 * 64 + j], res);
    float v = fmaxf(acc, 0.0f) + res;

    float s = v, q = v * v;
#pragma unroll
    for (int off = 16; off > 0; off >>= 1) {
        s += __shfl_xor_sync(0xffffffff, s, off);
        q += __shfl_xor_sync(0xffffffff, q, off);
    }
    __shared__ float sred[8], qred[8];
    int warp = tid >> 5;
    if ((tid & 31) == 0) { sred[warp] = s; qred[warp] = q; }
    __syncthreads();
    int grp = warp >> 1;
    float ts = sred[grp * 2] + sred[grp * 2 + 1];
    float tq = qred[grp * 2] + qred[grp * 2 + 1];
    float mu = ts * (1.0f / 64.0f);
    float var = tq * (1.0f / 64.0f) - mu * mu;
    float rstd = rsqrtf(var + 1e-5f);
    out[node * 64 + j] = (v - mu) * rstd * gam[j] + bet[j];
}

// ---------------- layers 1/2 gather-aggregate via CSR (no atomics) ----------------
__global__ void k_aggregate(const float* __restrict__ h) {
    int tid = threadIdx.x;
    int node = blockIdx.x * 4 + (tid >> 6);
    int j = tid & 63;
    if (node >= NN) return;
#pragma unroll
    for (int r = 0; r < 3; r++) {
        int bin = node * 3 + r;
        int a = g_off[bin], b = g_off[bin + 1];
        float acc0 = 0.0f, acc1 = 0.0f, acc2 = 0.0f, acc3 = 0.0f;
        int e = a;
        for (; e + 3 < b; e += 4) {
            int s0 = g_esrc[e], s1 = g_esrc[e + 1];
            int s2 = g_esrc[e + 2], s3 = g_esrc[e + 3];
            acc0 += h[s0 * 64 + j];
            acc1 += h[s1 * 64 + j];
            acc2 += h[s2 * 64 + j];
            acc3 += h[s3 * 64 + j];
        }
        for (; e < b; e++) acc0 += h[g_esrc[e] * 64 + j];
        g_agg[(r * NN + node) * 64 + j] = (acc0 + acc1) + (acc2 + acc3);
    }
}

// ---------------- tiled GEMM + fused relu/residual/LN epilogue ----------------
// [64 nodes x 256] @ [256 x 64]; mainloop = R8-proven. Epilogue: each node row's
// 64 cols live in 16 consecutive lanes (tx); n is uniform within each 16-lane
// group, and shuffles are unconditional -> full-warp convergence guaranteed.
__global__ void k_rgcn_gemm_ln(const float* __restrict__ xi,
                               const float* __restrict__ root, const float* __restrict__ W,
                               const float* __restrict__ bias,
                               const float* __restrict__ resid,
                               const float* __restrict__ gam, const float* __restrict__ bet,
                               float* __restrict__ out) {
    __shared__ float As[64 * 65];
    __shared__ float Bs[64 * 64];
    int tid = threadIdx.x;
    int n0 = blockIdx.x * 64;
    int tx = tid & 15, ty = tid >> 4;
    float acc[4][4] = {};

    for (int ko = 0; ko < 256; ko += 64) {
#pragma unroll
        for (int t = 0; t < 16; t++) {
            int idx = tid + t * 256;
            int row = idx >> 6, k = idx & 63;
            int n = n0 + row;
            float v = 0.0f;
            if (n < NN) {
                if (ko == 0) v = xi[n * 64 + k];
                else {
                    int r = (ko >> 6) - 1;
                    v = g_agg[(r * NN + n) * 64 + k] * g_inv[n * 3 + r];
                }
            }
            As[row * 65 + k] = v;
            float w;
            if (ko == 0) w = root[row * 64 + k];
            else {
                int r = (ko >> 6) - 1;
                w = W[r * 4096 + row * 64 + k];
            }
            Bs[row * 64 + k] = w;
        }
        __syncthreads();
#pragma unroll 8
        for (int kk = 0; kk < 64; kk++) {
            float a0 = As[(ty * 4 + 0) * 65 + kk];
            float a1 = As[(ty * 4 + 1) * 65 + kk];
            float a2 = As[(ty * 4 + 2) * 65 + kk];
            float a3 = As[(ty * 4 + 3) * 65 + kk];
            float4 b = *(const float4*)&Bs[kk * 64 + tx * 4];
            acc[0][0] = fmaf(a0, b.x, acc[0][0]); acc[0][1] = fmaf(a0, b.y, acc[0][1]);
            acc[0][2] = fmaf(a0, b.z, acc[0][2]); acc[0][3] = fmaf(a0, b.w, acc[0][3]);
            acc[1][0] = fmaf(a1, b.x, acc[1][0]); acc[1][1] = fmaf(a1, b.y, acc[1][1]);
            acc[1][2] = fmaf(a1, b.z, acc[1][2]); acc[1][3] = fmaf(a1, b.w, acc[1][3]);
            acc[2][0] = fmaf(a2, b.x, acc[2][0]); acc[2][1] = fmaf(a2, b.y, acc[2][1]);
            acc[2][2] = fmaf(a2, b.z, acc[2][2]); acc[2][3] = fmaf(a2, b.w, acc[2][3]);
            acc[3][0] = fmaf(a3, b.x, acc[3][0]); acc[3][1] = fmaf(a3, b.y, acc[3][1]);
            acc[3][2] = fmaf(a3, b.z, acc[3][2]); acc[3][3] = fmaf(a3, b.w, acc[3][3]);
        }
        __syncthreads();
    }

    // ---- fused epilogue: v = relu(acc+bias) + resid; LayerNorm over 64 cols ----
    float4 bv = *(const float4*)&bias[tx * 4];
    float4 gv = *(const float4*)&gam[tx * 4];
    float4 be = *(const float4*)&bet[tx * 4];
#pragma unroll
    for (int i = 0; i < 4; i++) {
        int n = n0 + ty * 4 + i;
        float4 rs = make_float4(0.f, 0.f, 0.f, 0.f);
        if (n < NN) rs = *(const float4*)&resid[n * 64 + tx * 4];
        float v0 = fmaxf(acc[i][0] + bv.x, 0.f) + rs.x;
        float v1 = fmaxf(acc[i][1] + bv.y, 0.f) + rs.y;
        float v2 = fmaxf(acc[i][2] + bv.z, 0.f) + rs.z;
        float v3 = fmaxf(acc[i][3] + bv.w, 0.f) + rs.w;
        float s = (v0 + v1) + (v2 + v3);
        float q = fmaf(v0, v0, fmaf(v1, v1, fmaf(v2, v2, v3 * v3)));
#pragma unroll
        for (int off = 8; off > 0; off >>= 1) {      // stays within 16-lane half
            s += __shfl_xor_sync(0xffffffff, s, off);
            q += __shfl_xor_sync(0xffffffff, q, off);
        }
        float mu = s * (1.0f / 64.0f);
        float var = q * (1.0f / 64.0f) - mu * mu;
        float rstd = rsqrtf(var + 1e-5f);
        if (n < NN) {
            *(float4*)&out[n * 64 + tx * 4] = make_float4(
                (v0 - mu) * rstd * gv.x + be.x, (v1 - mu) * rstd * gv.y + be.y,
                (v2 - mu) * rstd * gv.z + be.z, (v3 - mu) * rstd * gv.w + be.w);
        }
    }
}

// ---------------- pab as tiled GEMM: [50K x 64] @ [64 x 64] (R8-proven) ----------------
__global__ void k_pab2(const float* __restrict__ h3, const float* __restrict__ dw1,
                       const float* __restrict__ db1, float* __restrict__ pab) {
    __shared__ float As[64 * 65];
    __shared__ float Bs[64 * 64];
    int tid = threadIdx.x;
    int n0 = blockIdx.x * 64;
    int tx = tid & 15, ty = tid >> 4;
    float acc[4][4] = {};
#pragma unroll
    for (int t = 0; t < 16; t++) {
        int idx = tid + t * 256;
        int row = idx >> 6, k = idx & 63;
        int n = n0 + row;
        As[row * 65 + k] = (n < NN) ? h3[n * 64 + k] : 0.0f;
        Bs[row * 64 + k] = (k < 32) ? dw1[row * 32 + k] : dw1[(64 + row) * 32 + (k - 32)];
    }
    __syncthreads();
#pragma unroll 8
    for (int kk = 0; kk < 64; kk++) {
        float a0 = As[(ty * 4 + 0) * 65 + kk];
        float a1 = As[(ty * 4 + 1) * 65 + kk];
        float a2 = As[(ty * 4 + 2) * 65 + kk];
        float a3 = As[(ty * 4 + 3) * 65 + kk];
        float4 b = *(const float4*)&Bs[kk * 64 + tx * 4];
        acc[0][0] = fmaf(a0, b.x, acc[0][0]); acc[0][1] = fmaf(a0, b.y, acc[0][1]);
        acc[0][2] = fmaf(a0, b.z, acc[0][2]); acc[0][3] = fmaf(a0, b.w, acc[0][3]);
        acc[1][0] = fmaf(a1, b.x, acc[1][0]); acc[1][1] = fmaf(a1, b.y, acc[1][1]);
        acc[1][2] = fmaf(a1, b.z, acc[1][2]); acc[1][3] = fmaf(a1, b.w, acc[1][3]);
        acc[2][0] = fmaf(a2, b.x, acc[2][0]); acc[2][1] = fmaf(a2, b.y, acc[2][1]);
        acc[2][2] = fmaf(a2, b.z, acc[2][2]); acc[2][3] = fmaf(a2, b.w, acc[2][3]);
        acc[3][0] = fmaf(a3, b.x, acc[3][0]); acc[3][1] = fmaf(a3, b.y, acc[3][1]);
        acc[3][2] = fmaf(a3, b.z, acc[3][2]); acc[3][3] = fmaf(a3, b.w, acc[3][3]);
    }
    float4 bv = make_float4(0.f, 0.f, 0.f, 0.f);
    if (tx < 8) bv = *(const float4*)&db1[tx * 4];
#pragma unroll
    for (int i = 0; i < 4; i++) {
        int n = n0 + ty * 4 + i;
        if (n < NN) {
            float4 o = make_float4(acc[i][0] + bv.x, acc[i][1] + bv.y,
                                   acc[i][2] + bv.z, acc[i][3] + bv.w);
            *(float4*)&pab[n * 64 + tx * 4] = o;
        }
    }
}

// ---------------- decoder: block-level GEMM over 64-edge tiles (EXACT R8/R11) ----------------
// smem (floats): Bs[128*32] | F_T[128*66] | zS[32*66] | W2[512] | We[192]
//                | eS[384] | sIdx/dIdx int[64] each  => ~63.5KB, 3 CTAs/SM
#define DEC_SMEM_FLOATS (4096 + 8448 + 2112 + 512 + 192 + 384)
#define DEC_SMEM_BYTES  (DEC_SMEM_FLOATS * 4 + 128 * 4)

__global__ void k_decode_gemm(const int* __restrict__ ei, const float* __restrict__ ea,
                              const float* __restrict__ h3, const float* __restrict__ pab,
                              const float* __restrict__ dw1,
                              const float* __restrict__ dw2, const float* __restrict__ db2,
                              const float* __restrict__ dw3, const float* __restrict__ db3,
                              float* __restrict__ out) {
    extern __shared__ float smf[];
    float* Bs  = smf;               // [128][32] = dw1 rows 128..255
    float* F_T = Bs + 4096;         // [128][66] features^T
    float* zS  = F_T + 8448;        // [32][66]  z^T
    float* W2  = zS + 2112;         // [32][16]
    float* Wes = W2 + 512;          // [6][32]
    float* eS  = Wes + 192;         // [64][6]
    int* sIdx  = (int*)(eS + 384);  // [64]
    int* dIdx  = sIdx + 64;         // [64]

    int tid = threadIdx.x;
    for (int i = tid; i < 4096; i += 256) Bs[i] = dw1[128 * 32 + i];
    for (int i = tid; i < 512; i += 256) W2[i] = dw2[i];
    for (int i = tid; i < 192; i += 256) Wes[i] = dw1[256 * 32 + i];

    int kb = tid & 63, gb = tid >> 6;          // build phase
    int tx = tid & 15, ty = tid >> 4;          // layer1 tiling
    int c = 2 * tx, ty4 = ty * 4;
    int tx2 = tid & 7, ty2 = tid >> 3;         // layer2 tiling
    int c2 = 2 * tx2;
    float b2x = db2[c2], b2y = db2[c2 + 1];
    ull B2X, B2Y;
    asm("mov.b64 %0, {%1, %1};" : "=l"(B2X) : "f"(b2x));
    asm("mov.b64 %0, {%1, %1};" : "=l"(B2Y) : "f"(b2y));
    float w3x = dw3[c2], w3y = dw3[c2 + 1];
    float bias3 = db3[0];
    __syncthreads();

    for (int t = blockIdx.x; t < EE / 64; t += gridDim.x) {
        int e0 = t * 64;
        if (tid < 64) { sIdx[tid] = ei[e0 + tid]; dIdx[tid] = ei[EE + e0 + tid]; }
        for (int i = tid; i < 384; i += 256) eS[i] = ea[e0 * 6 + i];
        __syncthreads();

        // ---- build F_T: k<64 -> |hs-hd|, k>=64 -> hs*hd ----
#pragma unroll 4
        for (int p = 0; p < 16; p++) {
            int eL = p * 4 + gb;
            int sm = sIdx[eL], dm = dIdx[eL];
            float a = h3[sm * 64 + kb], b = h3[dm * 64 + kb];
            F_T[kb * 66 + eL]        = fabsf(a - b);
            F_T[(64 + kb) * 66 + eL] = a * b;
        }
        __syncthreads();

        // ---- layer 1: [64 x 128] @ [128 x 32] + pab + ea terms ----
        float initv[4][2];
#pragma unroll
        for (int i = 0; i < 4; i++) {
            int m = ty4 + i;
            int sm = sIdx[m], dm = dIdx[m];
            float2 pa = *(const float2*)&pab[sm * 64 + c];
            float2 pb = *(const float2*)&pab[dm * 64 + 32 + c];
            float v0 = pa.x + pb.x, v1 = pa.y + pb.y;
#pragma unroll
            for (int q = 0; q < 6; q++) {
                float eq = eS[m * 6 + q];
                float2 w = *(const float2*)&Wes[q * 32 + c];
                v0 = fmaf(eq, w.x, v0);
                v1 = fmaf(eq, w.y, v1);
            }
            initv[i][0] = v0; initv[i][1] = v1;
        }
        ull A00, A01, A10, A11;
        asm("mov.b64 %0, {%1, %2};" : "=l"(A00) : "f"(initv[0][0]), "f"(initv[1][0]));
        asm("mov.b64 %0, {%1, %2};" : "=l"(A01) : "f"(initv[0][1]), "f"(initv[1][1]));
        asm("mov.b64 %0, {%1, %2};" : "=l"(A10) : "f"(initv[2][0]), "f"(initv[3][0]));
        asm("mov.b64 %0, {%1, %2};" : "=l"(A11) : "f"(initv[2][1]), "f"(initv[3][1]));

#pragma unroll 8
        for (int kk = 0; kk < 128; kk++) {
            ull a01 = *(const ull*)&F_T[kk * 66 + ty4];
            ull a23 = *(const ull*)&F_T[kk * 66 + ty4 + 2];
            float2 b = *(const float2*)&Bs[kk * 32 + c];
            ull bx, by;
            asm("mov.b64 %0, {%1, %1};" : "=l"(bx) : "f"(b.x));
            asm("mov.b64 %0, {%1, %1};" : "=l"(by) : "f"(b.y));
            asm("fma.rn.f32x2 %0, %1, %2, %0;" : "+l"(A00) : "l"(a01), "l"(bx));
            asm("fma.rn.f32x2 %0, %1, %2, %0;" : "+l"(A01) : "l"(a01), "l"(by));
            asm("fma.rn.f32x2 %0, %1, %2, %0;" : "+l"(A10) : "l"(a23), "l"(bx));
            asm("fma.rn.f32x2 %0, %1, %2, %0;" : "+l"(A11) : "l"(a23), "l"(by));
        }
        {
            float u0, u1;
            asm("mov.b64 {%0, %1}, %2;" : "=f"(u0), "=f"(u1) : "l"(A00));
            *(float2*)&zS[c * 66 + ty4] = make_float2(fmaxf(u0, 0.f), fmaxf(u1, 0.f));
            asm("mov.b64 {%0, %1}, %2;" : "=f"(u0), "=f"(u1) : "l"(A10));
            *(float2*)&zS[c * 66 + ty4 + 2] = make_float2(fmaxf(u0, 0.f), fmaxf(u1, 0.f));
            asm("mov.b64 {%0, %1}, %2;" : "=f"(u0), "=f"(u1) : "l"(A01));
            *(float2*)&zS[(c + 1) * 66 + ty4] = make_float2(fmaxf(u0, 0.f), fmaxf(u1, 0.f));
            asm("mov.b64 {%0, %1}, %2;" : "=f"(u0), "=f"(u1) : "l"(A11));
            *(float2*)&zS[(c + 1) * 66 + ty4 + 2] = make_float2(fmaxf(u0, 0.f), fmaxf(u1, 0.f));
        }
        __syncthreads();

        // ---- layer 2: [64 x 32] @ [32 x 16], edge pair (2*ty2, 2*ty2+1) ----
        ull Z0 = B2X, Z1 = B2Y;
#pragma unroll 8
        for (int kk = 0; kk < 32; kk++) {
            ull zp = *(const ull*)&zS[kk * 66 + 2 * ty2];
            float2 w = *(const float2*)&W2[kk * 16 + c2];
            ull wx, wy;
            asm("mov.b64 %0, {%1, %1};" : "=l"(wx) : "f"(w.x));
            asm("mov.b64 %0, {%1, %1};" : "=l"(wy) : "f"(w.y));
            asm("fma.rn.f32x2 %0, %1, %2, %0;" : "+l"(Z0) : "l"(zp), "l"(wx));
            asm("fma.rn.f32x2 %0, %1, %2, %0;" : "+l"(Z1) : "l"(zp), "l"(wy));
        }
        float q00, q10, q01, q11;
        asm("mov.b64 {%0, %1}, %2;" : "=f"(q00), "=f"(q10) : "l"(Z0));
        asm("mov.b64 {%0, %1}, %2;" : "=f"(q01), "=f"(q11) : "l"(Z1));
        float o0 = fmaxf(q00, 0.f) * w3x + fmaxf(q01, 0.f) * w3y;
        float o1 = fmaxf(q10, 0.f) * w3x + fmaxf(q11, 0.f) * w3y;
        o0 += __shfl_xor_sync(0xffffffff, o0, 4);
        o0 += __shfl_xor_sync(0xffffffff, o0, 2);
        o0 += __shfl_xor_sync(0xffffffff, o0, 1);
        o1 += __shfl_xor_sync(0xffffffff, o1, 4);
        o1 += __shfl_xor_sync(0xffffffff, o1, 2);
        o1 += __shfl_xor_sync(0xffffffff, o1, 1);
        if (tx2 == 0) {
            out[e0 + 2 * ty2]     = o0 + bias3;
            out[e0 + 2 * ty2 + 1] = o1 + bias3;
        }
        __syncthreads();
    }
}

// ---------------- host launch ----------------
extern "C" void kernel_launch(void* const* d_in, const int* in_sizes, int n_in,
                              void* d_out, int out_size) {
    const float* x     = (const float*)d_in[0];
    const int*   ei    = (const int*)d_in[1];
    const float* ea    = (const float*)d_in[2];
    const float* w0    = (const float*)d_in[3];
    const float* root0 = (const float*)d_in[4];
    const float* b0    = (const float*)d_in[5];
    const float* w1    = (const float*)d_in[6];
    const float* root1 = (const float*)d_in[7];
    const float* b1    = (const float*)d_in[8];
    const float* w2    = (const float*)d_in[9];
    const float* root2 = (const float*)d_in[10];
    const float* b2    = (const float*)d_in[11];
    const float* lng0  = (const float*)d_in[12];
    const float* lnb0  = (const float*)d_in[13];
    const float* lng1  = (const float*)d_in[14];
    const float* lnb1  = (const float*)d_in[15];
    const float* lng2  = (const float*)d_in[16];
    const float* lnb2  = (const float*)d_in[17];
    const float* resw  = (const float*)d_in[18];
    const float* resb  = (const float*)d_in[19];
    const float* dw1   = (const float*)d_in[20];
    const float* db1   = (const float*)d_in[21];
    const float* dw2   = (const float*)d_in[22];
    const float* db2   = (const float*)d_in[23];
    const float* dw3   = (const float*)d_in[24];
    const float* db3   = (const float*)d_in[25];
    float* out = (float*)d_out;

    static int configured = 0;
    if (!configured) {
        cudaFuncSetAttribute(k_decode_gemm,
                             cudaFuncAttributeMaxDynamicSharedMemorySize, DEC_SMEM_BYTES);
        configured = 1;
    }

    void *p_cnt, *p_agg0, *p_h, *p_pab;
    cudaGetSymbolAddress(&p_cnt,  g_cnt);
    cudaGetSymbolAddress(&p_agg0, g_agg0);
    cudaGetSymbolAddress(&p_h,    g_h);
    cudaGetSymbolAddress(&p_pab,  g_pab);
    float* h1  = (float*)p_h;
    float* h2  = h1 + NN * 64;
    float* h3  = h2 + NN * 64;
    float* pab = (float*)p_pab;

    cudaMemsetAsync(p_cnt,  0, sizeof(int)   * NBINS);
    cudaMemsetAsync(p_agg0, 0, sizeof(float) * NN * 9);

    // fused: edge type + counts + layer0 scatter
    k_edge_prep<<<(EE + 255) / 256, 256>>>(ei, ea, x);

    // CSR build (scan3 also produces g_inv)
    k_scan1<<<SCAN_BLOCKS, 256>>>();
    k_scan2<<<1, 256>>>();
    k_scan3<<<SCAN_BLOCKS, 256>>>();
    k_fill<<<(EE + 255) / 256, 256>>>(ei);

    // layer 0
    k_node0<<<NN / 4, 256>>>(x, w0, root0, b0, resw, resb, lng0, lnb0, h1);

    // layer 1: aggregate + (GEMM ⊕ relu ⊕ residual ⊕ LN)
    k_aggregate<<<NN / 4, 256>>>(h1);
    k_rgcn_gemm_ln<<<(NN + 63) / 64, 256>>>(h1, root1, w1, b1, h1, lng1, lnb1, h2);

    // layer 2
    k_aggregate<<<NN / 4, 256>>>(h2);
    k_rgcn_gemm_ln<<<(NN + 63) / 64, 256>>>(h2, root2, w2, b2, h2, lng2, lnb2, h3);

    // decoder
    k_pab2<<<(NN + 63) / 64, 256>>>(h3, dw1, db1, pab);
    k_decode_gemm<<<444, 256, DEC_SMEM_BYTES>>>(ei, ea, h3, pab, dw1, dw2, db2, dw3, db3, out);
}